// round 15
// baseline (speedup 1.0000x reference)
#include <cuda_runtime.h>
#include <cuda_fp16.h>
#include <cstdint>

// ============================================================================
// y[8192,4096] = x[8192,4096] @ sign(W)[4096,4096], fp32 in/out.
// Plain-sm_103 target (no tcgen05). R15: ONE persistent fused kernel.
// Grid = 296 CTAs (2/SM exactly), 128 thr, CTA tile 128x128, warp tile 64x64,
// bulk-DMA stages from pre-swizzled blobs + mbarrier ring (R13/R14 mainloop,
// ~92% of the legacy-HMMA ceiling). NEW: each warp converts ~5 blobs (x->fp16,
// sign(W)^T->fp16, both smem-free) at the top of its first 6 iterations;
// per-ks gmem counters gate the DMA producer during each CTA's first tile.
// Conversion (45us of DRAM work) hides under first-tile compute.
// ============================================================================

#define MM 8192
#define NN 4096
#define KK 4096

#define TM 128
#define TN 128
#define TK 64
#define NSTAGE 3
#define NK (KK / TK)               // 64

#define BLOB_BYTES 16384
#define BLOB_ELEMS 8192
#define STAGE_BYTES (2 * BLOB_BYTES)
#define SMEM_TILES_OFF 1024
#define SMEM_TOTAL (SMEM_TILES_OFF + NSTAGE * STAGE_BYTES)   // 99328 -> 2 CTAs/SM

#define NTHREADS 128               // 4 warps
#define NPERS    296               // 148 SMs x 2 CTAs
#define NTILES   ((MM / TM) * (NN / TN))   // 2048
#define NJOBS    6144              // 4096 A-blobs + 2048 B-blobs
#define JSTRIDE  (NPERS * 4)       // 1184 warp-jobs per round

__device__ __align__(1024) __half g_xh[(size_t)MM * KK];   // A blobs
__device__ __align__(1024) __half g_sh[(size_t)NN * KK];   // B blobs
__device__ int g_ready[64];                                 // per-ks blob count

// ---------------------------------------------------------------------------
__device__ __forceinline__ uint32_t smem_u32(const void* p) {
    uint32_t a;
    asm("{ .reg .u64 t; cvta.to.shared.u64 t, %1; cvt.u32.u64 %0, t; }"
        : "=r"(a) : "l"(p));
    return a;
}
__device__ __forceinline__ uint32_t h2_u32(__half2 h) {
    return reinterpret_cast<uint32_t&>(h);
}

#define MBARRIER_INIT(addr, count) \
    asm volatile("mbarrier.init.shared.b64 [%0], %1;" \
        :: "r"((uint32_t)(addr)), "r"((uint32_t)(count)) : "memory")
#define MBARRIER_EXPECT_TX(addr, bytes) \
    asm volatile("mbarrier.arrive.expect_tx.shared.b64 _, [%0], %1;" \
        :: "r"((uint32_t)(addr)), "r"((uint32_t)(bytes)) : "memory")
#define MBARRIER_ARRIVE(addr) \
    asm volatile("mbarrier.arrive.shared.b64 _, [%0];" \
        :: "r"((uint32_t)(addr)) : "memory")
#define MBARRIER_WAIT_PARITY(mbar_smem_addr, phase_parity) do { \
    uint32_t _mbar = (uint32_t)(mbar_smem_addr); \
    uint32_t _parity = (uint32_t)(phase_parity); \
    uint32_t _done; \
    asm volatile( \
        "{\n\t.reg .pred p;\n\t" \
        "mbarrier.try_wait.parity.acquire.cta.shared::cta.b64 p, [%1], %2;\n\t" \
        "selp.b32 %0, 1, 0, p;\n\t}" \
        : "=r"(_done) : "r"(_mbar), "r"(_parity) : "memory"); \
    if (!_done) { \
        asm volatile( \
            "{\n\t.reg .pred P1;\n\t" \
            "WAIT_LOOP_%=:\n\t" \
            "mbarrier.try_wait.parity.acquire.cta.shared::cta.b64 P1, [%0], %1, 0x989680;\n\t" \
            "@P1 bra.uni WAIT_DONE_%=;\n\t" \
            "bra.uni WAIT_LOOP_%=;\n\t" \
            "WAIT_DONE_%=:\n\t}" \
            :: "r"(_mbar), "r"(_parity) : "memory"); \
    } \
} while (0)
#define FENCE_PROXY_ASYNC() \
    asm volatile("fence.proxy.async.shared::cta;" ::: "memory")
#define CP_BULK(dst, src, bytes, mbar) \
    asm volatile( \
        "cp.async.bulk.shared::cluster.global.mbarrier::complete_tx::bytes " \
        "[%0], [%1], %2, [%3];" \
        :: "r"((uint32_t)(dst)), "l"(src), "r"((uint32_t)(bytes)), \
           "r"((uint32_t)(mbar)) : "memory")

__device__ __forceinline__ void ldsm4(uint32_t* r, uint32_t addr) {
    asm volatile("ldmatrix.sync.aligned.m8n8.x4.shared.b16 {%0,%1,%2,%3}, [%4];"
        : "=r"(r[0]), "=r"(r[1]), "=r"(r[2]), "=r"(r[3]) : "r"(addr));
}
__device__ __forceinline__ void mma16816(float* c, const uint32_t* a, const uint32_t* b) {
    asm volatile(
        "mma.sync.aligned.m16n8k16.row.col.f32.f16.f16.f32 "
        "{%0,%1,%2,%3}, {%4,%5,%6,%7}, {%8,%9}, {%0,%1,%2,%3};"
        : "+f"(c[0]), "+f"(c[1]), "+f"(c[2]), "+f"(c[3])
        : "r"(a[0]), "r"(a[1]), "r"(a[2]), "r"(a[3]), "r"(b[0]), "r"(b[1]));
}

// ---------------------------------------------------------------------------
__global__ void k_zero() { if (threadIdx.x < 64) g_ready[threadIdx.x] = 0; }

// ---- warp-scope conversions (32 threads, smem-free) ----
__device__ void conv_a(const float* __restrict__ x, int tm, int ks, int lane) {
    const float* src = x + (size_t)tm * 128 * KK + ks * 64;
    char* dst = reinterpret_cast<char*>(g_xh + (size_t)(tm * 64 + ks) * BLOB_ELEMS);
#pragma unroll
    for (int i = 0; i < 32; ++i) {                 // 1024 chunks / 32 lanes
        int q = lane + i * 32;
        int r = q >> 3, c = q & 7;
        const float4* s4 = reinterpret_cast<const float4*>(src + (size_t)r * KK + c * 8);
        float4 v0 = s4[0], v1 = s4[1];
        uint4 w;
        w.x = h2_u32(__floats2half2_rn(v0.x, v0.y));
        w.y = h2_u32(__floats2half2_rn(v0.z, v0.w));
        w.z = h2_u32(__floats2half2_rn(v1.x, v1.y));
        w.w = h2_u32(__floats2half2_rn(v1.z, v1.w));
        int sc = c ^ (r & 7);
        *reinterpret_cast<uint4*>(dst + r * 128 + sc * 16) = w;
    }
}

__device__ void conv_b(const float* __restrict__ W, int tn, int ks, int lane) {
    // blob row n = sign(W[ks*64 + k][tn*128 + n]) for k = 0..63
    char* dst = reinterpret_cast<char*>(g_sh + (size_t)(tn * 64 + ks) * BLOB_ELEMS);
#pragma unroll
    for (int nn = 0; nn < 4; ++nn) {
        int n = lane + nn * 32;                    // 0..127, coalesced across warp
        const float* col = W + (size_t)(ks * 64) * NN + tn * 128 + n;
#pragma unroll
        for (int c = 0; c < 8; ++c) {
            union { __half h[8]; uint4 u; } w;
#pragma unroll
            for (int j = 0; j < 8; ++j) {
                float v = col[(size_t)(c * 8 + j) * NN];
                float s = (v > 0.f) ? 1.f : ((v < 0.f) ? -1.f : 0.f);
                w.h[j] = __float2half(s);
            }
            int sc = c ^ (n & 7);
            *reinterpret_cast<uint4*>(dst + n * 128 + sc * 16) = w.u;
        }
    }
}

// ---------------------------------------------------------------------------
// Fused persistent kernel
// ---------------------------------------------------------------------------
__global__ __launch_bounds__(NTHREADS, 2) __cluster_dims__(1, 1, 1)
void fused_kernel(const float* __restrict__ x, const float* __restrict__ W,
                  float* __restrict__ out) {
    extern __shared__ char smem[];
    const uint32_t sbase = smem_u32(smem);
    const uint32_t fullB  = sbase;
    const uint32_t emptyB = sbase + 24;
    const uint32_t tiles = sbase + SMEM_TILES_OFF;

    const int tid = threadIdx.x;
    const int wid = tid >> 5;
    const int lane = tid & 31;
    const int wm = wid & 1;
    const int wn = wid >> 1;
    const int bid = blockIdx.x;

    const int my_tiles = (NTILES - bid + NPERS - 1) / NPERS;   // 7 or 6
    const int G = my_tiles * 64;

    if (tid == 0) {
#pragma unroll
        for (int s = 0; s < NSTAGE; ++s) {
            MBARRIER_INIT(fullB + 8 * s, 1);
            MBARRIER_INIT(emptyB + 8 * s, 4);
        }
        FENCE_PROXY_ASYNC();
    }
    __syncthreads();

    const int a_row_base = wm * 64 + (lane & 15);
    const int a_hi = lane >> 4;
    const int b_n_base = wn * 64 + (lane & 7) + ((lane >> 4) << 3);
    const int b_hi = (lane >> 3) & 1;

    float acc[4][8][4];
#pragma unroll
    for (int mt = 0; mt < 4; ++mt)
#pragma unroll
        for (int nf = 0; nf < 8; ++nf)
#pragma unroll
            for (int v = 0; v < 4; ++v) acc[mt][nf][v] = 0.f;

    // tile index -> (pm, pn) with L2 grouping
    auto tile_pm_pn = [&](int t, int& pm, int& pn) {
        const int TILES_N = NN / TN;   // 32
        const int GROUP_M = 8;
        int group = t / (GROUP_M * TILES_N);
        int rem = t % (GROUP_M * TILES_N);
        pm = group * GROUP_M + (rem % GROUP_M);
        pn = rem / GROUP_M;
    };

    // producer: issue DMA for global iteration gg (stage gg%3)
    auto issue_stage = [&](int gg) {
        int ksq = gg & 63;
        if (gg < 64) {   // first tile only: gate on conversion completion
            volatile int* rd = g_ready;
            while (rd[ksq] < 96) {}
        }
        int tq = bid + (gg >> 6) * NPERS;
        int pmq, pnq;
        tile_pm_pn(tq, pmq, pnq);
        int s = gg % 3;
        uint32_t bar = fullB + 8 * s;
        MBARRIER_EXPECT_TX(bar, STAGE_BYTES);
        CP_BULK(tiles + s * STAGE_BYTES,
                g_xh + (size_t)(pmq * 64 + ksq) * BLOB_ELEMS, BLOB_BYTES, bar);
        CP_BULK(tiles + s * STAGE_BYTES + BLOB_BYTES,
                g_sh + (size_t)(pnq * 64 + ksq) * BLOB_ELEMS, BLOB_BYTES, bar);
    };

    int s_cur = 0, ph = 0;
    int es = 0, eph = 0;

    for (int g = 0; g < G; ++g) {
        // ---- conversion phase: one warp-job per iteration for g < 6 ----
        if (g < 6) {
            int jid = (bid * 4 + wid) + g * JSTRIDE;
            if (jid < NJOBS) {
                int ks = jid / 96, rr = jid % 96;
                if (rr < 64) conv_a(x, rr, ks, lane);
                else         conv_b(W, rr - 64, ks, lane);
                __syncwarp();
                if (lane == 0) {
                    __threadfence();
                    atomicAdd(&g_ready[ks], 1);
                }
            }
        }

        // ---- producer (tid 0) ----
        if (tid == 0) {
            if (g == 0) { issue_stage(0); issue_stage(1); }
            int gq = g + 2;
            if (gq < G) {
                if (g >= 1) {
                    int sn = gq % 3;
                    MBARRIER_WAIT_PARITY(emptyB + 8 * sn, eph);
                    if (++es == NSTAGE) { es = 0; eph ^= 1; }
                }
                issue_stage(gq);
            }
        }

        // ---- consumer ----
        MBARRIER_WAIT_PARITY(fullB + 8 * s_cur, ph);

        const uint32_t sa = tiles + s_cur * STAGE_BYTES;
        const uint32_t sb = sa + BLOB_BYTES;

#pragma unroll
        for (int ks = 0; ks < 4; ++ks) {
            uint32_t a[4][4], b[4][4];
#pragma unroll
            for (int mt = 0; mt < 4; ++mt) {
                int row = a_row_base + mt * 16;
                int ch = ks * 2 + a_hi;
                ldsm4(a[mt], sa + row * 128 + ((ch ^ (row & 7)) << 4));
            }
#pragma unroll
            for (int bq = 0; bq < 4; ++bq) {
                int n = b_n_base + bq * 16;
                int ch = ks * 2 + b_hi;
                ldsm4(b[bq], sb + n * 128 + ((ch ^ (n & 7)) << 4));
            }
#pragma unroll
            for (int mt = 0; mt < 4; ++mt)
#pragma unroll
                for (int nf = 0; nf < 8; ++nf)
                    mma16816(acc[mt][nf], a[mt], &b[nf >> 1][(nf & 1) * 2]);
        }

        __syncwarp();
        if (lane == 0) MBARRIER_ARRIVE(emptyB + 8 * s_cur);
        if (++s_cur == NSTAGE) { s_cur = 0; ph ^= 1; }

        // ---- per-tile epilogue ----
        if ((g & 63) == 63) {
            int t = bid + (g >> 6) * NPERS;
            int pm, pn;
            tile_pm_pn(t, pm, pn);
            int m0 = pm * TM, n0 = pn * TN;
#pragma unroll
            for (int mt = 0; mt < 4; ++mt) {
                int r0 = m0 + wm * 64 + mt * 16 + (lane >> 2);
#pragma unroll
                for (int nf = 0; nf < 8; ++nf) {
                    int c0 = n0 + wn * 64 + nf * 8 + (lane & 3) * 2;
                    float2 v0 = make_float2(acc[mt][nf][0], acc[mt][nf][1]);
                    float2 v1 = make_float2(acc[mt][nf][2], acc[mt][nf][3]);
                    *reinterpret_cast<float2*>(out + (size_t)r0 * NN + c0) = v0;
                    *reinterpret_cast<float2*>(out + (size_t)(r0 + 8) * NN + c0) = v1;
#pragma unroll
                    for (int v = 0; v < 4; ++v) acc[mt][nf][v] = 0.f;
                }
            }
        }
    }
}

// ---------------------------------------------------------------------------
extern "C" void kernel_launch(void* const* d_in, const int* in_sizes, int n_in,
                              void* d_out, int out_size) {
    const float* x;
    const float* W;
    if (in_sizes[0] == MM * KK) {
        x = (const float*)d_in[0];
        W = (const float*)d_in[1];
    } else {
        x = (const float*)d_in[1];
        W = (const float*)d_in[0];
    }

    k_zero<<<1, 64>>>();

    cudaFuncSetAttribute(fused_kernel, cudaFuncAttributeMaxDynamicSharedMemorySize, SMEM_TOTAL);
    fused_kernel<<<NPERS, NTHREADS, SMEM_TOTAL>>>(x, W, (float*)d_out);
}